// round 14
// baseline (speedup 1.0000x reference)
#include <cuda_runtime.h>
#include <math_constants.h>

// Problem shape (fixed by the reference): B=32768 rows, C=1000 cols.
#define B_ROWS 32768
#define C_COLS 1000
#define C_VEC  250          // float4s per row; row stride 4000 B (16B-aligned)
#define WARPS_PER_BLK 8
#define NBLOCKS 592         // 148 SMs x 4 resident CTAs -> single persistent wave
#define TOTAL_WARPS (NBLOCKS * WARPS_PER_BLK)   // 4736
#define REM_WARPS (B_ROWS % TOTAL_WARPS)        // 4352 warps get a 7th row

#define STAGES 4            // cp.async pipeline depth (slots mod 4, <=3 pending)

// Scratch (no device allocation allowed).
__device__ float g_block_sum[NBLOCKS];
__device__ unsigned int g_ticket = 0;   // re-armed by last block each run

// Persistent fused kernel, STATIC row assignment, cp.async-staged loads.
//  loss_row = sum_j softplus(x_j) - (any(label & x>0) ? sum_{label & x>0} x_j
//                                                      : max_{label} x_j)
// (gain_j == x_j and base == sum softplus(x_j) to ~1e-10 since |x| < ~6.)
// Branchless body, ONE MUFU/elem; ln(1+u) via deg-5 minimax (A&S 4.1.44).
// Loads go global->shared via cp.async (LDGSTS): in-flight data lives in
// SMEM instead of the register file, so ~3 KB/warp stays outstanding
// regardless of register pressure (vs ~160B/warp front-batched in RF).
__global__ void __launch_bounds__(256, 4)
fused_loss_kernel(const float* __restrict__ logits,
                  const float* __restrict__ labels,
                  float* __restrict__ d_out)
{
    // Per-warp staging: [stage][0..31]=x float4s, [stage][32..63]=m float4s.
    __shared__ float4 stage[WARPS_PER_BLK][STAGES][64];   // 32 KB

    const int warp  = threadIdx.x >> 5;
    const int lane  = threadIdx.x & 31;
    const int gwarp = blockIdx.x * WARPS_PER_BLK + warp;

    const int nrows   = 6 + (gwarp < REM_WARPS ? 1 : 0);
    const int total_t = nrows * 8;          // 8 pipeline iters per row

    float base_acc = 0.0f;   // per-lane sum of softplus over all my rows
    float gain_acc = 0.0f;   // lane 0: sum of per-row max_gain over my rows

    // Issue iteration t's loads (one commit group per t; empty group past end).
    auto issue_t = [&](int t) {
        if (t < total_t) {
            const int r = gwarp + (t >> 3) * TOTAL_WARPS;
            const int k = lane + (t & 7) * 32;
            if (k < C_VEC) {
                const float4* gx =
                    reinterpret_cast<const float4*>(logits + (size_t)r * C_COLS) + k;
                const float4* gm =
                    reinterpret_cast<const float4*>(labels + (size_t)r * C_COLS) + k;
                const unsigned sx =
                    (unsigned)__cvta_generic_to_shared(&stage[warp][t & (STAGES - 1)][lane]);
                const unsigned sm_ =
                    (unsigned)__cvta_generic_to_shared(&stage[warp][t & (STAGES - 1)][32 + lane]);
                asm volatile("cp.async.cg.shared.global [%0], [%1], 16;"
                             :: "r"(sx), "l"(gx));
                asm volatile("cp.async.cg.shared.global [%0], [%1], 16;"
                             :: "r"(sm_), "l"(gm));
            }
        }
        asm volatile("cp.async.commit_group;" ::: "memory");
    };

    // Prologue: 3 groups in flight.
    issue_t(0); issue_t(1); issue_t(2);

    float pos  = 0.0f;          // per-row: sum of positive gains on true labels
    float tmax = -CUDART_INF_F; // per-row: max gain on true labels

    for (int t = 0; t < total_t; ++t) {
        // <=2 groups pending -> group t is complete; its smem data visible.
        asm volatile("cp.async.wait_group 2;" ::: "memory");

        const int k = lane + (t & 7) * 32;
        if (k < C_VEC) {
            const float4 x4 = stage[warp][t & (STAGES - 1)][lane];
            const float4 m4 = stage[warp][t & (STAGES - 1)][32 + lane];
            const float xs[4] = {x4.x, x4.y, x4.z, x4.w};
            const float ms[4] = {m4.x, m4.y, m4.z, m4.w};
            #pragma unroll
            for (int j = 0; j < 4; ++j) {
                const float x  = xs[j];
                const float m  = ms[j];               // exactly 0.0f or 1.0f
                const float xp = fmaxf(x, 0.0f);
                const float u  = __expf(-fabsf(x));   // in (0, 1]
                float p = fmaf(0.03215845f, u, -0.13606275f);
                p = fmaf(p, u, 0.28947478f);
                p = fmaf(p, u, -0.49190896f);
                p = fmaf(p, u, 0.99949556f);
                base_acc += fmaf(p, u, xp);
                pos  = fmaf(m, xp, pos);              // adds x iff m & x>0
                tmax = fmaxf(tmax, fmaf(m - 1.0f, 1e30f, x));
            }
        }

        // Refill the pipeline before the row-end reduction (overlap).
        issue_t(t + 3);

        if ((t & 7) == 7) {
            // Row boundary: resolve this row's max_gain.
            // anyp == (warp-sum of pos) > 0 (pos is a sum of positives).
            if (__any_sync(0xFFFFFFFFu, pos > 0.0f)) {
                #pragma unroll
                for (int off = 16; off > 0; off >>= 1)
                    pos += __shfl_xor_sync(0xFFFFFFFFu, pos, off);
                if (lane == 0) gain_acc += pos;
            } else {
                // All gains on true labels negative (rare; full correctness).
                #pragma unroll
                for (int off = 16; off > 0; off >>= 1)
                    tmax = fmaxf(tmax, __shfl_xor_sync(0xFFFFFFFFu, tmax, off));
                if (lane == 0) gain_acc += tmax;
            }
            pos  = 0.0f;
            tmax = -CUDART_INF_F;
        }
    }
    asm volatile("cp.async.wait_group 0;" ::: "memory");

    // Fold base across the warp once, at the very end.
    #pragma unroll
    for (int off = 16; off > 0; off >>= 1)
        base_acc += __shfl_xor_sync(0xFFFFFFFFu, base_acc, off);

    // Block-level fold of the 8 warp partials (base - gain).
    __shared__ float s_warp[WARPS_PER_BLK];
    __shared__ bool  s_last;
    if (lane == 0) s_warp[warp] = base_acc - gain_acc;
    __syncthreads();

    if (threadIdx.x == 0) {
        float acc = 0.0f;
        #pragma unroll
        for (int w = 0; w < WARPS_PER_BLK; ++w) acc += s_warp[w];
        g_block_sum[blockIdx.x] = acc;
        __threadfence();                       // publish partial before ticket
        const unsigned t = atomicAdd(&g_ticket, 1u);
        s_last = (t == (unsigned)(NBLOCKS - 1));
    }
    __syncthreads();

    // Last-arriving block: fixed-order reduction of the 592 partials.
    if (s_last) {
        __shared__ float s[256];
        float acc = 0.0f;
        for (int i = threadIdx.x; i < NBLOCKS; i += 256)
            acc += g_block_sum[i];
        s[threadIdx.x] = acc;
        __syncthreads();
        #pragma unroll
        for (int off = 128; off > 0; off >>= 1) {
            if (threadIdx.x < off) s[threadIdx.x] += s[threadIdx.x + off];
            __syncthreads();
        }
        if (threadIdx.x == 0) {
            d_out[0] = s[0] * (1.0f / (float)B_ROWS);
            g_ticket = 0;                      // re-arm for graph replay
        }
    }
}

extern "C" void kernel_launch(void* const* d_in, const int* in_sizes, int n_in,
                              void* d_out, int out_size)
{
    const float* logits = (const float*)d_in[0];  // "output" [32768,1000] f32
    const float* labels = (const float*)d_in[1];  // "multilabels" [32768,1000] f32
    fused_loss_kernel<<<NBLOCKS, 256>>>(logits, labels, (float*)d_out);
}

// round 16
// speedup vs baseline: 1.0602x; 1.0602x over previous
#include <cuda_runtime.h>
#include <math_constants.h>

// Problem shape (fixed by the reference): B=32768 rows, C=1000 cols.
#define B_ROWS 32768
#define C_COLS 1000
#define C_VEC  250          // float4s per row; row stride 4000 B (16B-aligned)
#define WARPS_PER_BLK 8
#define NBLOCKS 592         // 148 SMs x 4 resident CTAs -> single persistent wave
#define TOTAL_WARPS (NBLOCKS * WARPS_PER_BLK)   // 4736

// Scratch (no device allocation allowed).
__device__ float g_block_sum[NBLOCKS];
__device__ unsigned int g_ticket = 0;   // re-armed by last block each run

// Persistent fused kernel, STATIC row assignment.
//  loss_row = sum_j softplus(x_j) - (any(label & x>0) ? sum_{label & x>0} x_j
//                                                      : max_{label} x_j)
// (gain_j == x_j and base == sum softplus(x_j) to ~1e-10 since |x| < ~6.)
// Inner loop is fully branchless (labels are exactly 0.0/1.0) and uses ONE
// MUFU per element: softplus(x) = max(x,0) + ln(1+u), u = exp(-|x|), with
// ln(1+u) evaluated by a degree-5 polynomial (A&S 4.1.44, |err| <= 1e-5 on
// [0,1] -> <= 0.01 absolute on a 1000-element row vs ~0.7 tolerance).
//
// Converged at the measured ~6.0 TB/s DRAM ceiling for this two-stream
// read-once pattern (falsified alternatives: evict-first policy, dynamic /
// hybrid work stealing, deeper cp.async pipelines, reduction/math trimming,
// higher occupancy — RF-capped at 32 warps/SM at the 64 regs the load
// batching requires).
__global__ void __launch_bounds__(256, 4)
fused_loss_kernel(const float* __restrict__ logits,
                  const float* __restrict__ labels,
                  float* __restrict__ d_out)
{
    const int warp  = threadIdx.x >> 5;
    const int lane  = threadIdx.x & 31;
    const int gwarp = blockIdx.x * WARPS_PER_BLK + warp;

    float base_acc = 0.0f;   // per-lane sum of softplus over all my rows
    float gain_acc = 0.0f;   // lane 0: sum of per-row max_gain over my rows

    for (int row = gwarp; row < B_ROWS; row += TOTAL_WARPS) {
        const float4* __restrict__ xr =
            reinterpret_cast<const float4*>(logits + (size_t)row * C_COLS);
        const float4* __restrict__ mr =
            reinterpret_cast<const float4*>(labels + (size_t)row * C_COLS);

        float pos  = 0.0f;          // sum of positive gains over true labels
        float tmax = -CUDART_INF_F; // max gain over true labels

        // 250 float4s over 32 lanes, fully unrolled (7 full + 26-lane tail)
        // so ptxas front-batches the LDG.128s (high MLP).
        #pragma unroll
        for (int i = 0; i < 8; ++i) {
            const int k = lane + i * 32;
            if (k < C_VEC) {
                const float4 x4 = __ldg(&xr[k]);
                const float4 m4 = __ldg(&mr[k]);
                const float xs[4] = {x4.x, x4.y, x4.z, x4.w};
                const float ms[4] = {m4.x, m4.y, m4.z, m4.w};
                #pragma unroll
                for (int j = 0; j < 4; ++j) {
                    const float x  = xs[j];
                    const float m  = ms[j];         // exactly 0.0f or 1.0f
                    const float xp = fmaxf(x, 0.0f);
                    const float u  = __expf(-fabsf(x));   // in (0, 1]
                    // ln(1+u): deg-5 minimax (Abramowitz-Stegun 4.1.44)
                    float p = fmaf(0.03215845f, u, -0.13606275f);
                    p = fmaf(p, u, 0.28947478f);
                    p = fmaf(p, u, -0.49190896f);
                    p = fmaf(p, u, 0.99949556f);
                    base_acc += fmaf(p, u, xp);
                    // branchless: m=1 -> contribute, m=0 -> no-op
                    pos  = fmaf(m, xp, pos);              // adds x iff m&x>0
                    tmax = fmaxf(tmax, fmaf(m - 1.0f, 1e30f, x));
                }
            }
        }

        // anyp == (warp-sum of pos) > 0 (pos is a sum of positives).
        if (__any_sync(0xFFFFFFFFu, pos > 0.0f)) {
            #pragma unroll
            for (int off = 16; off > 0; off >>= 1)
                pos += __shfl_xor_sync(0xFFFFFFFFu, pos, off);
            if (lane == 0) gain_acc += pos;
        } else {
            // All gains on true labels negative: max single gain (rare path,
            // kept for full correctness on adversarial inputs).
            #pragma unroll
            for (int off = 16; off > 0; off >>= 1)
                tmax = fmaxf(tmax, __shfl_xor_sync(0xFFFFFFFFu, tmax, off));
            if (lane == 0) gain_acc += tmax;
        }
    }

    // Fold base across the warp once, at the very end.
    #pragma unroll
    for (int off = 16; off > 0; off >>= 1)
        base_acc += __shfl_xor_sync(0xFFFFFFFFu, base_acc, off);

    // Block-level fold of the 8 warp partials (base - gain).
    __shared__ float s_warp[WARPS_PER_BLK];
    __shared__ bool  s_last;
    if (lane == 0) s_warp[warp] = base_acc - gain_acc;
    __syncthreads();

    if (threadIdx.x == 0) {
        float acc = 0.0f;
        #pragma unroll
        for (int w = 0; w < WARPS_PER_BLK; ++w) acc += s_warp[w];
        g_block_sum[blockIdx.x] = acc;
        __threadfence();                       // publish partial before ticket
        const unsigned t = atomicAdd(&g_ticket, 1u);
        s_last = (t == (unsigned)(NBLOCKS - 1));
    }
    __syncthreads();

    // Last-arriving block: fixed-order reduction of the 592 partials.
    if (s_last) {
        __shared__ float s[256];
        float acc = 0.0f;
        for (int i = threadIdx.x; i < NBLOCKS; i += 256)
            acc += g_block_sum[i];
        s[threadIdx.x] = acc;
        __syncthreads();
        #pragma unroll
        for (int off = 128; off > 0; off >>= 1) {
            if (threadIdx.x < off) s[threadIdx.x] += s[threadIdx.x + off];
            __syncthreads();
        }
        if (threadIdx.x == 0) {
            d_out[0] = s[0] * (1.0f / (float)B_ROWS);
            g_ticket = 0;                      // re-arm for graph replay
        }
    }
}

extern "C" void kernel_launch(void* const* d_in, const int* in_sizes, int n_in,
                              void* d_out, int out_size)
{
    const float* logits = (const float*)d_in[0];  // "output" [32768,1000] f32
    const float* labels = (const float*)d_in[1];  // "multilabels" [32768,1000] f32
    fused_loss_kernel<<<NBLOCKS, 256>>>(logits, labels, (float*)d_out);
}